// round 6
// baseline (speedup 1.0000x reference)
#include <cuda_runtime.h>

#define MN 50000      // nodes
#define KF 256        // in features
#define NF 128        // out features
#define NE 800000     // edges

#define NB_SCAN ((MN + 1023) / 1024)   // 49 scan blocks

// scratch
__device__ float g_support[(size_t)MN * NF];   // x @ W  (25.6 MB)
__device__ int   g_cnt[MN];                    // per-row edge counts
__device__ int   g_incl[MN];                   // within-block inclusive scan
__device__ int   g_bsum[64];                   // per-block sums
__device__ int   g_bpre[64];                   // exclusive prefix of block sums
__device__ int   g_cur[MN];                    // running fill cursor
__device__ int   g_off[MN + 1];                // CSR row offsets
__device__ int   g_eid[NE];                    // edge ids grouped by row

// ---------------------------------------------------------------------------
// SGEMM: support[MN,NF] = x[MN,KF] @ w[KF,NF]
// 128x128 tile, BK=8, 256 threads, 8x8 per thread, double-buffered SMEM.
// ---------------------------------------------------------------------------
__global__ __launch_bounds__(256, 2) void gemm_kernel(const float* __restrict__ x,
                                                      const float* __restrict__ w) {
    __shared__ float As[2][8][128];   // [buf][k][m]
    __shared__ float Bs[2][8][128];   // [buf][k][n]

    const int tid = threadIdx.x;
    const int tx = tid & 15;          // n group
    const int ty = tid >> 4;          // m group
    const int blockRow = blockIdx.x * 128;

    const int aRow = tid >> 1;                       // 0..127
    const int aCol = (tid & 1) * 4;                  // 0 or 4
    const int aRowG = min(blockRow + aRow, MN - 1);  // clamp; store guarded below
    const int bRow = tid >> 5;                       // 0..7 (k)
    const int bCol = (tid & 31) * 4;                 // 0..124

    float acc[8][8];
    #pragma unroll
    for (int i = 0; i < 8; i++)
        #pragma unroll
        for (int j = 0; j < 8; j++) acc[i][j] = 0.0f;

    // prologue: load tile 0
    float4 av = *reinterpret_cast<const float4*>(&x[(size_t)aRowG * KF + aCol]);
    float4 bv = *reinterpret_cast<const float4*>(&w[(size_t)bRow * NF + bCol]);
    As[0][aCol + 0][aRow] = av.x;
    As[0][aCol + 1][aRow] = av.y;
    As[0][aCol + 2][aRow] = av.z;
    As[0][aCol + 3][aRow] = av.w;
    *reinterpret_cast<float4*>(&Bs[0][bRow][bCol]) = bv;
    __syncthreads();

    int buf = 0;
    for (int kt = 0; kt < KF; kt += 8) {
        const bool has_next = (kt + 8) < KF;
        if (has_next) {
            av = *reinterpret_cast<const float4*>(&x[(size_t)aRowG * KF + kt + 8 + aCol]);
            bv = *reinterpret_cast<const float4*>(&w[(size_t)(kt + 8 + bRow) * NF + bCol]);
        }

        #pragma unroll
        for (int k = 0; k < 8; k++) {
            float a[8], b[8];
            #pragma unroll
            for (int i = 0; i < 8; i++) a[i] = As[buf][k][ty * 8 + i];
            #pragma unroll
            for (int j = 0; j < 8; j++) b[j] = Bs[buf][k][tx * 8 + j];
            #pragma unroll
            for (int i = 0; i < 8; i++)
                #pragma unroll
                for (int j = 0; j < 8; j++)
                    acc[i][j] = fmaf(a[i], b[j], acc[i][j]);
        }

        if (has_next) {
            const int nb = buf ^ 1;
            As[nb][aCol + 0][aRow] = av.x;
            As[nb][aCol + 1][aRow] = av.y;
            As[nb][aCol + 2][aRow] = av.z;
            As[nb][aCol + 3][aRow] = av.w;
            *reinterpret_cast<float4*>(&Bs[nb][bRow][bCol]) = bv;
            __syncthreads();
            buf = nb;
        }
    }

    #pragma unroll
    for (int i = 0; i < 8; i++) {
        int row = blockRow + ty * 8 + i;
        if (row < MN) {
            float* dst = &g_support[(size_t)row * NF + tx * 8];
            *reinterpret_cast<float4*>(dst)     = make_float4(acc[i][0], acc[i][1], acc[i][2], acc[i][3]);
            *reinterpret_cast<float4*>(dst + 4) = make_float4(acc[i][4], acc[i][5], acc[i][6], acc[i][7]);
        }
    }
}

// ---------------------------------------------------------------------------
// CSR build
// ---------------------------------------------------------------------------
__global__ __launch_bounds__(256) void zero_cnt_kernel() {
    int i = blockIdx.x * 256 + threadIdx.x;
    if (i < MN) g_cnt[i] = 0;
}

__global__ __launch_bounds__(256) void hist_kernel(const int* __restrict__ rows) {
    int e = blockIdx.x * 256 + threadIdx.x;
    if (e < NE) atomicAdd(&g_cnt[rows[e]], 1);
}

// Phase A: per-block inclusive scan of 1024 counts (coalesced)
__global__ __launch_bounds__(1024) void scanA_kernel() {
    __shared__ int sm[1024];
    const int t = threadIdx.x;
    const int i = blockIdx.x * 1024 + t;
    const int v = (i < MN) ? g_cnt[i] : 0;
    sm[t] = v;
    __syncthreads();
    #pragma unroll
    for (int off = 1; off < 1024; off <<= 1) {
        int u = (t >= off) ? sm[t - off] : 0;
        __syncthreads();
        sm[t] += u;
        __syncthreads();
    }
    if (i < MN) g_incl[i] = sm[t];
    if (t == 1023) g_bsum[blockIdx.x] = sm[1023];
}

// Phase B: scan the 49 block sums (1 block, 64 threads)
__global__ __launch_bounds__(64) void scanB_kernel() {
    __shared__ int sm[64];
    const int t = threadIdx.x;
    const int v = (t < NB_SCAN) ? g_bsum[t] : 0;
    sm[t] = v;
    __syncthreads();
    #pragma unroll
    for (int off = 1; off < 64; off <<= 1) {
        int u = (t >= off) ? sm[t - off] : 0;
        __syncthreads();
        sm[t] += u;
        __syncthreads();
    }
    g_bpre[t] = sm[t] - v;   // exclusive prefix
}

// Phase C: write exclusive offsets + cursors
__global__ __launch_bounds__(1024) void scanC_kernel() {
    const int i = blockIdx.x * 1024 + threadIdx.x;
    if (i < MN) {
        const int off = g_incl[i] - g_cnt[i] + g_bpre[blockIdx.x];
        g_off[i] = off;
        g_cur[i] = off;
    }
    if (i == 0) g_off[MN] = NE;
}

__global__ __launch_bounds__(256) void fill_kernel(const int* __restrict__ rows) {
    int e = blockIdx.x * 256 + threadIdx.x;
    if (e < NE) {
        int pos = atomicAdd(&g_cur[rows[e]], 1);
        g_eid[pos] = e;
    }
}

// ---------------------------------------------------------------------------
// Accumulate: one warp per output row. Lane handles 4 cols (float4).
// ---------------------------------------------------------------------------
__global__ __launch_bounds__(256) void acc_kernel(const float* __restrict__ vals,
                                                  const int* __restrict__ cols,
                                                  float* __restrict__ out) {
    const int r = blockIdx.x * 8 + (threadIdx.x >> 5);
    if (r >= MN) return;
    const int lane = threadIdx.x & 31;

    const int beg = g_off[r];
    const int end = g_off[r + 1];

    float4 acc = make_float4(0.f, 0.f, 0.f, 0.f);

    int i = beg;
    for (; i + 1 < end; i += 2) {
        const int e0 = __ldg(&g_eid[i]);
        const int e1 = __ldg(&g_eid[i + 1]);
        const float v0 = __ldg(&vals[e0]);
        const float v1 = __ldg(&vals[e1]);
        const int c0 = __ldg(&cols[e0]);
        const int c1 = __ldg(&cols[e1]);
        const float4 s0 = __ldg(reinterpret_cast<const float4*>(g_support + (size_t)c0 * NF) + lane);
        const float4 s1 = __ldg(reinterpret_cast<const float4*>(g_support + (size_t)c1 * NF) + lane);
        acc.x = fmaf(v0, s0.x, acc.x);
        acc.y = fmaf(v0, s0.y, acc.y);
        acc.z = fmaf(v0, s0.z, acc.z);
        acc.w = fmaf(v0, s0.w, acc.w);
        acc.x = fmaf(v1, s1.x, acc.x);
        acc.y = fmaf(v1, s1.y, acc.y);
        acc.z = fmaf(v1, s1.z, acc.z);
        acc.w = fmaf(v1, s1.w, acc.w);
    }
    if (i < end) {
        const int e0 = __ldg(&g_eid[i]);
        const float v0 = __ldg(&vals[e0]);
        const int c0 = __ldg(&cols[e0]);
        const float4 s0 = __ldg(reinterpret_cast<const float4*>(g_support + (size_t)c0 * NF) + lane);
        acc.x = fmaf(v0, s0.x, acc.x);
        acc.y = fmaf(v0, s0.y, acc.y);
        acc.z = fmaf(v0, s0.z, acc.z);
        acc.w = fmaf(v0, s0.w, acc.w);
    }

    float4 o;
    o.x = fmaxf(acc.x, 0.f);
    o.y = fmaxf(acc.y, 0.f);
    o.z = fmaxf(acc.z, 0.f);
    o.w = fmaxf(acc.w, 0.f);
    *(reinterpret_cast<float4*>(out + (size_t)r * NF) + lane) = o;
}

// ---------------------------------------------------------------------------
// Launch: fork CSR build onto a side stream so it overlaps the GEMM.
// Stream/events are created once, on the (uncaptured) first call.
// ---------------------------------------------------------------------------
static cudaStream_t s_side = nullptr;
static cudaEvent_t  s_evFork = nullptr;
static cudaEvent_t  s_evJoin = nullptr;

extern "C" void kernel_launch(void* const* d_in, const int* in_sizes, int n_in,
                              void* d_out, int out_size) {
    const float* x    = (const float*)d_in[0];
    const float* w    = (const float*)d_in[1];
    const float* vals = (const float*)d_in[2];
    const int*   rows = (const int*)d_in[3];
    const int*   cols = (const int*)d_in[4];
    float* out = (float*)d_out;

    if (!s_side) {
        cudaStreamCreateWithFlags(&s_side, cudaStreamNonBlocking);
        cudaEventCreateWithFlags(&s_evFork, cudaEventDisableTiming);
        cudaEventCreateWithFlags(&s_evJoin, cudaEventDisableTiming);
    }

    // fork: CSR build on side stream
    cudaEventRecord(s_evFork, 0);
    cudaStreamWaitEvent(s_side, s_evFork, 0);

    zero_cnt_kernel<<<(MN + 255) / 256, 256, 0, s_side>>>();
    hist_kernel<<<(NE + 255) / 256, 256, 0, s_side>>>(rows);
    scanA_kernel<<<NB_SCAN, 1024, 0, s_side>>>();
    scanB_kernel<<<1, 64, 0, s_side>>>();
    scanC_kernel<<<NB_SCAN, 1024, 0, s_side>>>();
    fill_kernel<<<(NE + 255) / 256, 256, 0, s_side>>>(rows);
    cudaEventRecord(s_evJoin, s_side);

    // main stream: GEMM (independent of CSR build)
    gemm_kernel<<<(MN + 127) / 128, 256>>>(x, w);

    // join, then accumulate
    cudaStreamWaitEvent(0, s_evJoin, 0);
    acc_kernel<<<(MN + 7) / 8, 256>>>(vals, cols, out);
}

// round 7
// speedup vs baseline: 1.0623x; 1.0623x over previous
#include <cuda_runtime.h>

#define MN 50000      // nodes
#define KF 256        // in features
#define NF 128        // out features
#define NE 800000     // edges

#define NB_SCAN ((MN + 1023) / 1024)   // 49 scan blocks

// scratch
__device__ float g_support[(size_t)MN * NF];   // x @ W  (25.6 MB)
__device__ int   g_cnt[MN];
__device__ int   g_incl[MN];
__device__ int   g_bsum[64];
__device__ int   g_bpre[64];
__device__ int   g_cur[MN];
__device__ int   g_off[MN + 1];
__device__ int   g_eid[NE];

// ---------------------------------------------------------------------------
// tf32 helpers
// ---------------------------------------------------------------------------
__device__ __forceinline__ unsigned tf32_of(float f) {
    unsigned r;
    asm("cvt.rna.tf32.f32 %0, %1;" : "=r"(r) : "f"(f));
    return r;
}

__device__ __forceinline__ void mma_tf32(float d[4], const unsigned a[4],
                                         unsigned b0, unsigned b1) {
    asm volatile(
        "mma.sync.aligned.m16n8k8.row.col.f32.tf32.tf32.f32 "
        "{%0,%1,%2,%3}, {%4,%5,%6,%7}, {%8,%9}, {%0,%1,%2,%3};"
        : "+f"(d[0]), "+f"(d[1]), "+f"(d[2]), "+f"(d[3])
        : "r"(a[0]), "r"(a[1]), "r"(a[2]), "r"(a[3]), "r"(b0), "r"(b1));
}

// ---------------------------------------------------------------------------
// GEMM: support[MN,NF] = x[MN,KF] @ w[KF,NF]  via split-tf32 tensor-core MMA.
// 128x128 CTA tile, BK=16, 8 warps (4Mx2N), warp tile 32x64.
// D += Ahi*Bhi + Ahi*Blo + Alo*Bhi   (fp32-accurate to ~1e-6)
// ---------------------------------------------------------------------------
__global__ __launch_bounds__(256, 2) void gemm_kernel(const float* __restrict__ x,
                                                      const float* __restrict__ w) {
    __shared__ unsigned As_hi[128][20], As_lo[128][20];   // [m][k], pad 16->20
    __shared__ unsigned Bs_hi[16][136], Bs_lo[16][136];   // [k][n], pad 128->136

    const int tid = threadIdx.x;
    const int wid = tid >> 5;
    const int lane = tid & 31;
    const int grp = lane >> 2;     // 0..7
    const int tig = lane & 3;      // 0..3
    const int warpM = wid >> 1;    // 0..3  (32 rows each)
    const int warpN = wid & 1;     // 0..1  (64 cols each)
    const int blockRow = blockIdx.x * 128;

    // global-load mappings (per thread: 2 float4 of x, 2 float4 of w)
    const int xr0 = tid >> 2;                 // 0..63
    const int xr1 = xr0 + 64;                 // 64..127
    const int xc  = (tid & 3) * 4;            // 0,4,8,12
    const int xg0 = min(blockRow + xr0, MN - 1);
    const int xg1 = min(blockRow + xr1, MN - 1);
    const int wr  = tid >> 5;                 // 0..7
    const int wc  = (tid & 31) * 4;           // 0..124

    float d[2][8][4];
    #pragma unroll
    for (int mt = 0; mt < 2; mt++)
        #pragma unroll
        for (int nt = 0; nt < 8; nt++)
            #pragma unroll
            for (int i = 0; i < 4; i++) d[mt][nt][i] = 0.0f;

    // prologue: load tile 0
    float4 xa = *reinterpret_cast<const float4*>(&x[(size_t)xg0 * KF + xc]);
    float4 xb = *reinterpret_cast<const float4*>(&x[(size_t)xg1 * KF + xc]);
    float4 wa = *reinterpret_cast<const float4*>(&w[(size_t)wr * NF + wc]);
    float4 wb = *reinterpret_cast<const float4*>(&w[(size_t)(wr + 8) * NF + wc]);

    #pragma unroll 1
    for (int kt = 0; kt < KF; kt += 16) {
        // stage current tile to smem (split hi/lo)
        {
            const float fx[8] = {xa.x, xa.y, xa.z, xa.w, xb.x, xb.y, xb.z, xb.w};
            #pragma unroll
            for (int i = 0; i < 4; i++) {
                unsigned h = tf32_of(fx[i]);
                As_hi[xr0][xc + i] = h;
                As_lo[xr0][xc + i] = tf32_of(fx[i] - __uint_as_float(h));
            }
            #pragma unroll
            for (int i = 0; i < 4; i++) {
                unsigned h = tf32_of(fx[4 + i]);
                As_hi[xr1][xc + i] = h;
                As_lo[xr1][xc + i] = tf32_of(fx[4 + i] - __uint_as_float(h));
            }
            const float fw[8] = {wa.x, wa.y, wa.z, wa.w, wb.x, wb.y, wb.z, wb.w};
            #pragma unroll
            for (int i = 0; i < 4; i++) {
                unsigned h = tf32_of(fw[i]);
                Bs_hi[wr][wc + i] = h;
                Bs_lo[wr][wc + i] = tf32_of(fw[i] - __uint_as_float(h));
            }
            #pragma unroll
            for (int i = 0; i < 4; i++) {
                unsigned h = tf32_of(fw[4 + i]);
                Bs_hi[wr + 8][wc + i] = h;
                Bs_lo[wr + 8][wc + i] = tf32_of(fw[4 + i] - __uint_as_float(h));
            }
        }
        __syncthreads();

        // prefetch next tile into registers
        const bool has_next = (kt + 16) < KF;
        if (has_next) {
            xa = *reinterpret_cast<const float4*>(&x[(size_t)xg0 * KF + kt + 16 + xc]);
            xb = *reinterpret_cast<const float4*>(&x[(size_t)xg1 * KF + kt + 16 + xc]);
            wa = *reinterpret_cast<const float4*>(&w[(size_t)(kt + 16 + wr) * NF + wc]);
            wb = *reinterpret_cast<const float4*>(&w[(size_t)(kt + 16 + wr + 8) * NF + wc]);
        }

        // compute on staged tile
        #pragma unroll
        for (int k0 = 0; k0 < 16; k0 += 8) {
            unsigned ah[2][4], al[2][4];
            #pragma unroll
            for (int mt = 0; mt < 2; mt++) {
                const int rb = warpM * 32 + mt * 16;
                ah[mt][0] = As_hi[rb + grp][k0 + tig];
                ah[mt][1] = As_hi[rb + grp + 8][k0 + tig];
                ah[mt][2] = As_hi[rb + grp][k0 + tig + 4];
                ah[mt][3] = As_hi[rb + grp + 8][k0 + tig + 4];
                al[mt][0] = As_lo[rb + grp][k0 + tig];
                al[mt][1] = As_lo[rb + grp + 8][k0 + tig];
                al[mt][2] = As_lo[rb + grp][k0 + tig + 4];
                al[mt][3] = As_lo[rb + grp + 8][k0 + tig + 4];
            }
            #pragma unroll
            for (int nt = 0; nt < 8; nt++) {
                const int cb = warpN * 64 + nt * 8 + grp;
                const unsigned bh0 = Bs_hi[k0 + tig][cb];
                const unsigned bh1 = Bs_hi[k0 + tig + 4][cb];
                const unsigned bl0 = Bs_lo[k0 + tig][cb];
                const unsigned bl1 = Bs_lo[k0 + tig + 4][cb];
                #pragma unroll
                for (int mt = 0; mt < 2; mt++) {
                    mma_tf32(d[mt][nt], ah[mt], bl0, bl1);   // hi*lo
                    mma_tf32(d[mt][nt], al[mt], bh0, bh1);   // lo*hi
                    mma_tf32(d[mt][nt], ah[mt], bh0, bh1);   // hi*hi
                }
            }
        }
        __syncthreads();
    }

    // epilogue: write support
    #pragma unroll
    for (int mt = 0; mt < 2; mt++) {
        const int r0 = blockRow + warpM * 32 + mt * 16 + grp;
        const int r1 = r0 + 8;
        #pragma unroll
        for (int nt = 0; nt < 8; nt++) {
            const int col = warpN * 64 + nt * 8 + 2 * tig;
            if (r0 < MN)
                *reinterpret_cast<float2*>(&g_support[(size_t)r0 * NF + col]) =
                    make_float2(d[mt][nt][0], d[mt][nt][1]);
            if (r1 < MN)
                *reinterpret_cast<float2*>(&g_support[(size_t)r1 * NF + col]) =
                    make_float2(d[mt][nt][2], d[mt][nt][3]);
        }
    }
}

// ---------------------------------------------------------------------------
// CSR build
// ---------------------------------------------------------------------------
__global__ __launch_bounds__(256) void zero_cnt_kernel() {
    int i = blockIdx.x * 256 + threadIdx.x;
    if (i < MN) g_cnt[i] = 0;
}

__global__ __launch_bounds__(256) void hist_kernel(const int* __restrict__ rows) {
    int e = blockIdx.x * 256 + threadIdx.x;
    if (e < NE) atomicAdd(&g_cnt[rows[e]], 1);
}

__global__ __launch_bounds__(1024) void scanA_kernel() {
    __shared__ int sm[1024];
    const int t = threadIdx.x;
    const int i = blockIdx.x * 1024 + t;
    const int v = (i < MN) ? g_cnt[i] : 0;
    sm[t] = v;
    __syncthreads();
    #pragma unroll
    for (int off = 1; off < 1024; off <<= 1) {
        int u = (t >= off) ? sm[t - off] : 0;
        __syncthreads();
        sm[t] += u;
        __syncthreads();
    }
    if (i < MN) g_incl[i] = sm[t];
    if (t == 1023) g_bsum[blockIdx.x] = sm[1023];
}

__global__ __launch_bounds__(64) void scanB_kernel() {
    __shared__ int sm[64];
    const int t = threadIdx.x;
    const int v = (t < NB_SCAN) ? g_bsum[t] : 0;
    sm[t] = v;
    __syncthreads();
    #pragma unroll
    for (int off = 1; off < 64; off <<= 1) {
        int u = (t >= off) ? sm[t - off] : 0;
        __syncthreads();
        sm[t] += u;
        __syncthreads();
    }
    g_bpre[t] = sm[t] - v;
}

__global__ __launch_bounds__(1024) void scanC_kernel() {
    const int i = blockIdx.x * 1024 + threadIdx.x;
    if (i < MN) {
        const int off = g_incl[i] - g_cnt[i] + g_bpre[blockIdx.x];
        g_off[i] = off;
        g_cur[i] = off;
    }
    if (i == 0) g_off[MN] = NE;
}

__global__ __launch_bounds__(256) void fill_kernel(const int* __restrict__ rows) {
    int e = blockIdx.x * 256 + threadIdx.x;
    if (e < NE) {
        int pos = atomicAdd(&g_cur[rows[e]], 1);
        g_eid[pos] = e;
    }
}

// ---------------------------------------------------------------------------
// Accumulate: one warp per output row, register accumulation, fused ReLU.
// ---------------------------------------------------------------------------
__global__ __launch_bounds__(256) void acc_kernel(const float* __restrict__ vals,
                                                  const int* __restrict__ cols,
                                                  float* __restrict__ out) {
    const int r = blockIdx.x * 8 + (threadIdx.x >> 5);
    if (r >= MN) return;
    const int lane = threadIdx.x & 31;

    const int beg = g_off[r];
    const int end = g_off[r + 1];

    float4 acc = make_float4(0.f, 0.f, 0.f, 0.f);

    int i = beg;
    for (; i + 1 < end; i += 2) {
        const int e0 = __ldg(&g_eid[i]);
        const int e1 = __ldg(&g_eid[i + 1]);
        const float v0 = __ldg(&vals[e0]);
        const float v1 = __ldg(&vals[e1]);
        const int c0 = __ldg(&cols[e0]);
        const int c1 = __ldg(&cols[e1]);
        const float4 s0 = __ldg(reinterpret_cast<const float4*>(g_support + (size_t)c0 * NF) + lane);
        const float4 s1 = __ldg(reinterpret_cast<const float4*>(g_support + (size_t)c1 * NF) + lane);
        acc.x = fmaf(v0, s0.x, acc.x);
        acc.y = fmaf(v0, s0.y, acc.y);
        acc.z = fmaf(v0, s0.z, acc.z);
        acc.w = fmaf(v0, s0.w, acc.w);
        acc.x = fmaf(v1, s1.x, acc.x);
        acc.y = fmaf(v1, s1.y, acc.y);
        acc.z = fmaf(v1, s1.z, acc.z);
        acc.w = fmaf(v1, s1.w, acc.w);
    }
    if (i < end) {
        const int e0 = __ldg(&g_eid[i]);
        const float v0 = __ldg(&vals[e0]);
        const int c0 = __ldg(&cols[e0]);
        const float4 s0 = __ldg(reinterpret_cast<const float4*>(g_support + (size_t)c0 * NF) + lane);
        acc.x = fmaf(v0, s0.x, acc.x);
        acc.y = fmaf(v0, s0.y, acc.y);
        acc.z = fmaf(v0, s0.z, acc.z);
        acc.w = fmaf(v0, s0.w, acc.w);
    }

    float4 o;
    o.x = fmaxf(acc.x, 0.f);
    o.y = fmaxf(acc.y, 0.f);
    o.z = fmaxf(acc.z, 0.f);
    o.w = fmaxf(acc.w, 0.f);
    *(reinterpret_cast<float4*>(out + (size_t)r * NF) + lane) = o;
}

// ---------------------------------------------------------------------------
// Launch: CSR build forked onto a side stream, overlapped with the GEMM.
// ---------------------------------------------------------------------------
static cudaStream_t s_side = nullptr;
static cudaEvent_t  s_evFork = nullptr;
static cudaEvent_t  s_evJoin = nullptr;

extern "C" void kernel_launch(void* const* d_in, const int* in_sizes, int n_in,
                              void* d_out, int out_size) {
    const float* x    = (const float*)d_in[0];
    const float* w    = (const float*)d_in[1];
    const float* vals = (const float*)d_in[2];
    const int*   rows = (const int*)d_in[3];
    const int*   cols = (const int*)d_in[4];
    float* out = (float*)d_out;

    if (!s_side) {
        cudaStreamCreateWithFlags(&s_side, cudaStreamNonBlocking);
        cudaEventCreateWithFlags(&s_evFork, cudaEventDisableTiming);
        cudaEventCreateWithFlags(&s_evJoin, cudaEventDisableTiming);
    }

    // fork: CSR build on side stream
    cudaEventRecord(s_evFork, 0);
    cudaStreamWaitEvent(s_side, s_evFork, 0);

    zero_cnt_kernel<<<(MN + 255) / 256, 256, 0, s_side>>>();
    hist_kernel<<<(NE + 255) / 256, 256, 0, s_side>>>(rows);
    scanA_kernel<<<NB_SCAN, 1024, 0, s_side>>>();
    scanB_kernel<<<1, 64, 0, s_side>>>();
    scanC_kernel<<<NB_SCAN, 1024, 0, s_side>>>();
    fill_kernel<<<(NE + 255) / 256, 256, 0, s_side>>>(rows);
    cudaEventRecord(s_evJoin, s_side);

    // main stream: GEMM (independent of CSR build)
    gemm_kernel<<<(MN + 127) / 128, 256>>>(x, w);

    // join, then accumulate
    cudaStreamWaitEvent(0, s_evJoin, 0);
    acc_kernel<<<(MN + 7) / 8, 256>>>(vals, cols, out);
}

// round 8
// speedup vs baseline: 1.3892x; 1.3078x over previous
#include <cuda_runtime.h>
#include <cuda_bf16.h>

#define MN 50000      // nodes
#define KF 256        // in features
#define NF 128        // out features
#define NE 800000     // edges

#define NB_SCAN ((MN + 1023) / 1024)   // 49 scan blocks

// scratch
__device__ float g_support[(size_t)MN * NF];   // x @ W  (25.6 MB)
__device__ int   g_cnt[MN];
__device__ int   g_incl[MN];
__device__ int   g_bsum[64];
__device__ int   g_bpre[64];
__device__ int   g_cur[MN];
__device__ int   g_off[MN + 1];
__device__ int   g_eid[NE];

// ---------------------------------------------------------------------------
// bf16 split helpers: f = hi + lo (each bf16), pack two k-adjacent elements
// into one 32-bit word (low half = even k, high half = odd k).
// ---------------------------------------------------------------------------
__device__ __forceinline__ void split2(float f0, float f1, unsigned& hi, unsigned& lo) {
    __nv_bfloat16 h0 = __float2bfloat16(f0);
    __nv_bfloat16 h1 = __float2bfloat16(f1);
    __nv_bfloat16 l0 = __float2bfloat16(f0 - __bfloat162float(h0));
    __nv_bfloat16 l1 = __float2bfloat16(f1 - __bfloat162float(h1));
    hi = (unsigned)__bfloat16_as_ushort(h0) | ((unsigned)__bfloat16_as_ushort(h1) << 16);
    lo = (unsigned)__bfloat16_as_ushort(l0) | ((unsigned)__bfloat16_as_ushort(l1) << 16);
}

__device__ __forceinline__ void mma_bf16(float d[4], const unsigned a[4],
                                         unsigned b0, unsigned b1) {
    asm volatile(
        "mma.sync.aligned.m16n8k16.row.col.f32.bf16.bf16.f32 "
        "{%0,%1,%2,%3}, {%4,%5,%6,%7}, {%8,%9}, {%0,%1,%2,%3};"
        : "+f"(d[0]), "+f"(d[1]), "+f"(d[2]), "+f"(d[3])
        : "r"(a[0]), "r"(a[1]), "r"(a[2]), "r"(a[3]), "r"(b0), "r"(b1));
}

// ---------------------------------------------------------------------------
// GEMM: support[MN,NF] = x[MN,KF] @ w[KF,NF]  via split-bf16 m16n8k16 MMA.
// 128x128 CTA tile, BK=16, 8 warps (4Mx2N), warp tile 32x64.
// D += Ahi*Bhi + Ahi*Blo + Alo*Bhi   (rel err ~1e-5)
// SMEM words (k-packed pairs): A[m][k/2] stride 12, B[k/2][n] stride 136.
// ---------------------------------------------------------------------------
__global__ __launch_bounds__(256, 2) void gemm_kernel(const float* __restrict__ x,
                                                      const float* __restrict__ w) {
    __shared__ unsigned As_hi[128][12], As_lo[128][12];   // [m][k/2], 8 words + pad 4
    __shared__ unsigned Bs_hi[8][136], Bs_lo[8][136];     // [k/2][n], 128 + pad 8

    const int tid = threadIdx.x;
    const int wid = tid >> 5;
    const int lane = tid & 31;
    const int grp = lane >> 2;     // 0..7
    const int tig = lane & 3;      // 0..3
    const int warpM = wid >> 1;    // 0..3  (32 rows each)
    const int warpN = wid & 1;     // 0..1  (64 cols each)
    const int blockRow = blockIdx.x * 128;

    // x-load mapping: per thread 2 float4 (rows xr0/xr1, 4 consecutive k)
    const int xr0 = tid >> 2;                 // 0..63
    const int xr1 = xr0 + 64;                 // 64..127
    const int xc  = (tid & 3) * 4;            // k offset within tile: 0,4,8,12
    const int xw  = (tid & 3) * 2;            // word col: 0,2,4,6
    const int xg0 = min(blockRow + xr0, MN - 1);
    const int xg1 = min(blockRow + xr1, MN - 1);
    // w-load mapping: per thread 2 k-adjacent rows (even/odd), 4 cols
    const int wr0 = (tid >> 5) * 2;           // even k row: 0,2,..,14
    const int wc  = (tid & 31) * 4;           // 0..124

    float d[2][8][4];
    #pragma unroll
    for (int mt = 0; mt < 2; mt++)
        #pragma unroll
        for (int nt = 0; nt < 8; nt++)
            #pragma unroll
            for (int i = 0; i < 4; i++) d[mt][nt][i] = 0.0f;

    // prologue: load tile 0
    float4 xa = *reinterpret_cast<const float4*>(&x[(size_t)xg0 * KF + xc]);
    float4 xb = *reinterpret_cast<const float4*>(&x[(size_t)xg1 * KF + xc]);
    float4 wa = *reinterpret_cast<const float4*>(&w[(size_t)wr0 * NF + wc]);
    float4 wb = *reinterpret_cast<const float4*>(&w[(size_t)(wr0 + 1) * NF + wc]);

    #pragma unroll 1
    for (int kt = 0; kt < KF; kt += 16) {
        // stage current tile (split + k-pack)
        {
            unsigned h, l;
            split2(xa.x, xa.y, h, l); As_hi[xr0][xw + 0] = h; As_lo[xr0][xw + 0] = l;
            split2(xa.z, xa.w, h, l); As_hi[xr0][xw + 1] = h; As_lo[xr0][xw + 1] = l;
            split2(xb.x, xb.y, h, l); As_hi[xr1][xw + 0] = h; As_lo[xr1][xw + 0] = l;
            split2(xb.z, xb.w, h, l); As_hi[xr1][xw + 1] = h; As_lo[xr1][xw + 1] = l;
            const int bw = tid >> 5;   // word row = k/2
            split2(wa.x, wb.x, h, l); Bs_hi[bw][wc + 0] = h; Bs_lo[bw][wc + 0] = l;
            split2(wa.y, wb.y, h, l); Bs_hi[bw][wc + 1] = h; Bs_lo[bw][wc + 1] = l;
            split2(wa.z, wb.z, h, l); Bs_hi[bw][wc + 2] = h; Bs_lo[bw][wc + 2] = l;
            split2(wa.w, wb.w, h, l); Bs_hi[bw][wc + 3] = h; Bs_lo[bw][wc + 3] = l;
        }
        __syncthreads();

        // prefetch next tile into registers
        const bool has_next = (kt + 16) < KF;
        if (has_next) {
            xa = *reinterpret_cast<const float4*>(&x[(size_t)xg0 * KF + kt + 16 + xc]);
            xb = *reinterpret_cast<const float4*>(&x[(size_t)xg1 * KF + kt + 16 + xc]);
            wa = *reinterpret_cast<const float4*>(&w[(size_t)(kt + 16 + wr0) * NF + wc]);
            wb = *reinterpret_cast<const float4*>(&w[(size_t)(kt + 16 + wr0 + 1) * NF + wc]);
        }

        // A fragments for both m-tiles (hi + lo)
        unsigned ah[2][4], al[2][4];
        #pragma unroll
        for (int mt = 0; mt < 2; mt++) {
            const int rb = warpM * 32 + mt * 16;
            ah[mt][0] = As_hi[rb + grp][tig];
            ah[mt][1] = As_hi[rb + grp + 8][tig];
            ah[mt][2] = As_hi[rb + grp][tig + 4];
            ah[mt][3] = As_hi[rb + grp + 8][tig + 4];
            al[mt][0] = As_lo[rb + grp][tig];
            al[mt][1] = As_lo[rb + grp + 8][tig];
            al[mt][2] = As_lo[rb + grp][tig + 4];
            al[mt][3] = As_lo[rb + grp + 8][tig + 4];
        }

        #pragma unroll
        for (int nt = 0; nt < 8; nt++) {
            const int cb = warpN * 64 + nt * 8 + grp;
            const unsigned bh0 = Bs_hi[tig][cb];
            const unsigned bh1 = Bs_hi[tig + 4][cb];
            const unsigned bl0 = Bs_lo[tig][cb];
            const unsigned bl1 = Bs_lo[tig + 4][cb];
            #pragma unroll
            for (int mt = 0; mt < 2; mt++) {
                mma_bf16(d[mt][nt], ah[mt], bl0, bl1);   // hi*lo
                mma_bf16(d[mt][nt], al[mt], bh0, bh1);   // lo*hi
                mma_bf16(d[mt][nt], ah[mt], bh0, bh1);   // hi*hi
            }
        }
        __syncthreads();
    }

    // epilogue: write support
    #pragma unroll
    for (int mt = 0; mt < 2; mt++) {
        const int r0 = blockRow + warpM * 32 + mt * 16 + grp;
        const int r1 = r0 + 8;
        #pragma unroll
        for (int nt = 0; nt < 8; nt++) {
            const int col = warpN * 64 + nt * 8 + 2 * tig;
            if (r0 < MN)
                *reinterpret_cast<float2*>(&g_support[(size_t)r0 * NF + col]) =
                    make_float2(d[mt][nt][0], d[mt][nt][1]);
            if (r1 < MN)
                *reinterpret_cast<float2*>(&g_support[(size_t)r1 * NF + col]) =
                    make_float2(d[mt][nt][2], d[mt][nt][3]);
        }
    }
}

// ---------------------------------------------------------------------------
// CSR build
// ---------------------------------------------------------------------------
__global__ __launch_bounds__(256) void zero_cnt_kernel() {
    int i = blockIdx.x * 256 + threadIdx.x;
    if (i < MN) g_cnt[i] = 0;
}

__global__ __launch_bounds__(256) void hist_kernel(const int* __restrict__ rows) {
    int e = blockIdx.x * 256 + threadIdx.x;
    if (e < NE) atomicAdd(&g_cnt[rows[e]], 1);
}

__global__ __launch_bounds__(1024) void scanA_kernel() {
    __shared__ int sm[1024];
    const int t = threadIdx.x;
    const int i = blockIdx.x * 1024 + t;
    const int v = (i < MN) ? g_cnt[i] : 0;
    sm[t] = v;
    __syncthreads();
    #pragma unroll
    for (int off = 1; off < 1024; off <<= 1) {
        int u = (t >= off) ? sm[t - off] : 0;
        __syncthreads();
        sm[t] += u;
        __syncthreads();
    }
    if (i < MN) g_incl[i] = sm[t];
    if (t == 1023) g_bsum[blockIdx.x] = sm[1023];
}

__global__ __launch_bounds__(64) void scanB_kernel() {
    __shared__ int sm[64];
    const int t = threadIdx.x;
    const int v = (t < NB_SCAN) ? g_bsum[t] : 0;
    sm[t] = v;
    __syncthreads();
    #pragma unroll
    for (int off = 1; off < 64; off <<= 1) {
        int u = (t >= off) ? sm[t - off] : 0;
        __syncthreads();
        sm[t] += u;
        __syncthreads();
    }
    g_bpre[t] = sm[t] - v;
}

__global__ __launch_bounds__(1024) void scanC_kernel() {
    const int i = blockIdx.x * 1024 + threadIdx.x;
    if (i < MN) {
        const int off = g_incl[i] - g_cnt[i] + g_bpre[blockIdx.x];
        g_off[i] = off;
        g_cur[i] = off;
    }
    if (i == 0) g_off[MN] = NE;
}

__global__ __launch_bounds__(256) void fill_kernel(const int* __restrict__ rows) {
    int e = blockIdx.x * 256 + threadIdx.x;
    if (e < NE) {
        int pos = atomicAdd(&g_cur[rows[e]], 1);
        g_eid[pos] = e;
    }
}

// ---------------------------------------------------------------------------
// Accumulate: one warp per output row, register accumulation, fused ReLU.
// ---------------------------------------------------------------------------
__global__ __launch_bounds__(256) void acc_kernel(const float* __restrict__ vals,
                                                  const int* __restrict__ cols,
                                                  float* __restrict__ out) {
    const int r = blockIdx.x * 8 + (threadIdx.x >> 5);
    if (r >= MN) return;
    const int lane = threadIdx.x & 31;

    const int beg = g_off[r];
    const int end = g_off[r + 1];

    float4 acc = make_float4(0.f, 0.f, 0.f, 0.f);

    int i = beg;
    for (; i + 1 < end; i += 2) {
        const int e0 = __ldg(&g_eid[i]);
        const int e1 = __ldg(&g_eid[i + 1]);
        const float v0 = __ldg(&vals[e0]);
        const float v1 = __ldg(&vals[e1]);
        const int c0 = __ldg(&cols[e0]);
        const int c1 = __ldg(&cols[e1]);
        const float4 s0 = __ldg(reinterpret_cast<const float4*>(g_support + (size_t)c0 * NF) + lane);
        const float4 s1 = __ldg(reinterpret_cast<const float4*>(g_support + (size_t)c1 * NF) + lane);
        acc.x = fmaf(v0, s0.x, acc.x);
        acc.y = fmaf(v0, s0.y, acc.y);
        acc.z = fmaf(v0, s0.z, acc.z);
        acc.w = fmaf(v0, s0.w, acc.w);
        acc.x = fmaf(v1, s1.x, acc.x);
        acc.y = fmaf(v1, s1.y, acc.y);
        acc.z = fmaf(v1, s1.z, acc.z);
        acc.w = fmaf(v1, s1.w, acc.w);
    }
    if (i < end) {
        const int e0 = __ldg(&g_eid[i]);
        const float v0 = __ldg(&vals[e0]);
        const int c0 = __ldg(&cols[e0]);
        const float4 s0 = __ldg(reinterpret_cast<const float4*>(g_support + (size_t)c0 * NF) + lane);
        acc.x = fmaf(v0, s0.x, acc.x);
        acc.y = fmaf(v0, s0.y, acc.y);
        acc.z = fmaf(v0, s0.z, acc.z);
        acc.w = fmaf(v0, s0.w, acc.w);
    }

    float4 o;
    o.x = fmaxf(acc.x, 0.f);
    o.y = fmaxf(acc.y, 0.f);
    o.z = fmaxf(acc.z, 0.f);
    o.w = fmaxf(acc.w, 0.f);
    *(reinterpret_cast<float4*>(out + (size_t)r * NF) + lane) = o;
}

// ---------------------------------------------------------------------------
// Launch: CSR build forked onto a side stream, overlapped with the GEMM.
// ---------------------------------------------------------------------------
static cudaStream_t s_side = nullptr;
static cudaEvent_t  s_evFork = nullptr;
static cudaEvent_t  s_evJoin = nullptr;

extern "C" void kernel_launch(void* const* d_in, const int* in_sizes, int n_in,
                              void* d_out, int out_size) {
    const float* x    = (const float*)d_in[0];
    const float* w    = (const float*)d_in[1];
    const float* vals = (const float*)d_in[2];
    const int*   rows = (const int*)d_in[3];
    const int*   cols = (const int*)d_in[4];
    float* out = (float*)d_out;

    if (!s_side) {
        cudaStreamCreateWithFlags(&s_side, cudaStreamNonBlocking);
        cudaEventCreateWithFlags(&s_evFork, cudaEventDisableTiming);
        cudaEventCreateWithFlags(&s_evJoin, cudaEventDisableTiming);
    }

    // fork: CSR build on side stream
    cudaEventRecord(s_evFork, 0);
    cudaStreamWaitEvent(s_side, s_evFork, 0);

    zero_cnt_kernel<<<(MN + 255) / 256, 256, 0, s_side>>>();
    hist_kernel<<<(NE + 255) / 256, 256, 0, s_side>>>(rows);
    scanA_kernel<<<NB_SCAN, 1024, 0, s_side>>>();
    scanB_kernel<<<1, 64, 0, s_side>>>();
    scanC_kernel<<<NB_SCAN, 1024, 0, s_side>>>();
    fill_kernel<<<(NE + 255) / 256, 256, 0, s_side>>>(rows);
    cudaEventRecord(s_evJoin, s_side);

    // main stream: GEMM (independent of CSR build)
    gemm_kernel<<<(MN + 127) / 128, 256>>>(x, w);

    // join, then accumulate
    cudaStreamWaitEvent(0, s_evJoin, 0);
    acc_kernel<<<(MN + 7) / 8, 256>>>(vals, cols, out);
}

// round 10
// speedup vs baseline: 1.4100x; 1.0149x over previous
#include <cuda_runtime.h>
#include <cuda_bf16.h>
#include <cuda_fp16.h>

#define MN 50000      // nodes
#define KF 256        // in features
#define NF 128        // out features
#define NE 800000     // edges

#define NB_SCAN ((MN + 1023) / 1024)   // 49 scan blocks

// scratch
__device__ __half g_support_h[(size_t)MN * NF];   // x @ W in fp16 (12.8 MB)
__device__ int   g_cnt[MN];
__device__ int   g_incl[MN];
__device__ int   g_bsum[64];
__device__ int   g_bpre[64];
__device__ int   g_cur[MN];
__device__ int   g_off[MN + 1];
__device__ int   g_eid[NE];

// ---------------------------------------------------------------------------
// bf16 split helpers: f = hi + lo (each bf16), pack two k-adjacent elements
// into one 32-bit word (low half = even k, high half = odd k).
// ---------------------------------------------------------------------------
__device__ __forceinline__ void split2(float f0, float f1, unsigned& hi, unsigned& lo) {
    __nv_bfloat16 h0 = __float2bfloat16(f0);
    __nv_bfloat16 h1 = __float2bfloat16(f1);
    __nv_bfloat16 l0 = __float2bfloat16(f0 - __bfloat162float(h0));
    __nv_bfloat16 l1 = __float2bfloat16(f1 - __bfloat162float(h1));
    hi = (unsigned)__bfloat16_as_ushort(h0) | ((unsigned)__bfloat16_as_ushort(h1) << 16);
    lo = (unsigned)__bfloat16_as_ushort(l0) | ((unsigned)__bfloat16_as_ushort(l1) << 16);
}

__device__ __forceinline__ void mma_bf16(float d[4], const unsigned a[4],
                                         unsigned b0, unsigned b1) {
    asm volatile(
        "mma.sync.aligned.m16n8k16.row.col.f32.bf16.bf16.f32 "
        "{%0,%1,%2,%3}, {%4,%5,%6,%7}, {%8,%9}, {%0,%1,%2,%3};"
        : "+f"(d[0]), "+f"(d[1]), "+f"(d[2]), "+f"(d[3])
        : "r"(a[0]), "r"(a[1]), "r"(a[2]), "r"(a[3]), "r"(b0), "r"(b1));
}

// ---------------------------------------------------------------------------
// GEMM: support[MN,NF] = x[MN,KF] @ w[KF,NF]  via split-bf16 m16n8k16 MMA.
// 128x128 CTA tile, BK=16, 8 warps (4Mx2N), warp tile 32x64.
// D += Ahi*Bhi + Ahi*Blo + Alo*Bhi   (rel err ~1e-5); output stored fp16.
// ---------------------------------------------------------------------------
__global__ __launch_bounds__(256, 2) void gemm_kernel(const float* __restrict__ x,
                                                      const float* __restrict__ w) {
    __shared__ unsigned As_hi[128][12], As_lo[128][12];   // [m][k/2], 8 words + pad 4
    __shared__ unsigned Bs_hi[8][136], Bs_lo[8][136];     // [k/2][n], 128 + pad 8

    const int tid = threadIdx.x;
    const int wid = tid >> 5;
    const int lane = tid & 31;
    const int grp = lane >> 2;     // 0..7
    const int tig = lane & 3;      // 0..3
    const int warpM = wid >> 1;    // 0..3  (32 rows each)
    const int warpN = wid & 1;     // 0..1  (64 cols each)
    const int blockRow = blockIdx.x * 128;

    const int xr0 = tid >> 2;                 // 0..63
    const int xr1 = xr0 + 64;                 // 64..127
    const int xc  = (tid & 3) * 4;            // k offset: 0,4,8,12
    const int xw  = (tid & 3) * 2;            // word col: 0,2,4,6
    const int xg0 = min(blockRow + xr0, MN - 1);
    const int xg1 = min(blockRow + xr1, MN - 1);
    const int wr0 = (tid >> 5) * 2;           // even k row
    const int wc  = (tid & 31) * 4;           // 0..124

    float d[2][8][4];
    #pragma unroll
    for (int mt = 0; mt < 2; mt++)
        #pragma unroll
        for (int nt = 0; nt < 8; nt++)
            #pragma unroll
            for (int i = 0; i < 4; i++) d[mt][nt][i] = 0.0f;

    // prologue: load tile 0
    float4 xa = *reinterpret_cast<const float4*>(&x[(size_t)xg0 * KF + xc]);
    float4 xb = *reinterpret_cast<const float4*>(&x[(size_t)xg1 * KF + xc]);
    float4 wa = *reinterpret_cast<const float4*>(&w[(size_t)wr0 * NF + wc]);
    float4 wb = *reinterpret_cast<const float4*>(&w[(size_t)(wr0 + 1) * NF + wc]);

    #pragma unroll 1
    for (int kt = 0; kt < KF; kt += 16) {
        // stage current tile (split + k-pack)
        {
            unsigned h, l;
            split2(xa.x, xa.y, h, l); As_hi[xr0][xw + 0] = h; As_lo[xr0][xw + 0] = l;
            split2(xa.z, xa.w, h, l); As_hi[xr0][xw + 1] = h; As_lo[xr0][xw + 1] = l;
            split2(xb.x, xb.y, h, l); As_hi[xr1][xw + 0] = h; As_lo[xr1][xw + 0] = l;
            split2(xb.z, xb.w, h, l); As_hi[xr1][xw + 1] = h; As_lo[xr1][xw + 1] = l;
            const int bw = tid >> 5;   // word row = k/2
            split2(wa.x, wb.x, h, l); Bs_hi[bw][wc + 0] = h; Bs_lo[bw][wc + 0] = l;
            split2(wa.y, wb.y, h, l); Bs_hi[bw][wc + 1] = h; Bs_lo[bw][wc + 1] = l;
            split2(wa.z, wb.z, h, l); Bs_hi[bw][wc + 2] = h; Bs_lo[bw][wc + 2] = l;
            split2(wa.w, wb.w, h, l); Bs_hi[bw][wc + 3] = h; Bs_lo[bw][wc + 3] = l;
        }
        __syncthreads();

        // prefetch next tile into registers
        const bool has_next = (kt + 16) < KF;
        if (has_next) {
            xa = *reinterpret_cast<const float4*>(&x[(size_t)xg0 * KF + kt + 16 + xc]);
            xb = *reinterpret_cast<const float4*>(&x[(size_t)xg1 * KF + kt + 16 + xc]);
            wa = *reinterpret_cast<const float4*>(&w[(size_t)(kt + 16 + wr0) * NF + wc]);
            wb = *reinterpret_cast<const float4*>(&w[(size_t)(kt + 16 + wr0 + 1) * NF + wc]);
        }

        // A fragments for both m-tiles (hi + lo)
        unsigned ah[2][4], al[2][4];
        #pragma unroll
        for (int mt = 0; mt < 2; mt++) {
            const int rb = warpM * 32 + mt * 16;
            ah[mt][0] = As_hi[rb + grp][tig];
            ah[mt][1] = As_hi[rb + grp + 8][tig];
            ah[mt][2] = As_hi[rb + grp][tig + 4];
            ah[mt][3] = As_hi[rb + grp + 8][tig + 4];
            al[mt][0] = As_lo[rb + grp][tig];
            al[mt][1] = As_lo[rb + grp + 8][tig];
            al[mt][2] = As_lo[rb + grp][tig + 4];
            al[mt][3] = As_lo[rb + grp + 8][tig + 4];
        }

        #pragma unroll
        for (int nt = 0; nt < 8; nt++) {
            const int cb = warpN * 64 + nt * 8 + grp;
            const unsigned bh0 = Bs_hi[tig][cb];
            const unsigned bh1 = Bs_hi[tig + 4][cb];
            const unsigned bl0 = Bs_lo[tig][cb];
            const unsigned bl1 = Bs_lo[tig + 4][cb];
            #pragma unroll
            for (int mt = 0; mt < 2; mt++) {
                mma_bf16(d[mt][nt], ah[mt], bl0, bl1);   // hi*lo
                mma_bf16(d[mt][nt], al[mt], bh0, bh1);   // lo*hi
                mma_bf16(d[mt][nt], ah[mt], bh0, bh1);   // hi*hi
            }
        }
        __syncthreads();
    }

    // epilogue: write support as fp16 (half2 stores)
    #pragma unroll
    for (int mt = 0; mt < 2; mt++) {
        const int r0 = blockRow + warpM * 32 + mt * 16 + grp;
        const int r1 = r0 + 8;
        #pragma unroll
        for (int nt = 0; nt < 8; nt++) {
            const int col = warpN * 64 + nt * 8 + 2 * tig;
            if (r0 < MN)
                *reinterpret_cast<__half2*>(&g_support_h[(size_t)r0 * NF + col]) =
                    __floats2half2_rn(d[mt][nt][0], d[mt][nt][1]);
            if (r1 < MN)
                *reinterpret_cast<__half2*>(&g_support_h[(size_t)r1 * NF + col]) =
                    __floats2half2_rn(d[mt][nt][2], d[mt][nt][3]);
        }
    }
}

// ---------------------------------------------------------------------------
// CSR build
// ---------------------------------------------------------------------------
__global__ __launch_bounds__(256) void zero_cnt_kernel() {
    int i = blockIdx.x * 256 + threadIdx.x;
    if (i < MN) g_cnt[i] = 0;
}

__global__ __launch_bounds__(256) void hist_kernel(const int* __restrict__ rows) {
    int e = blockIdx.x * 256 + threadIdx.x;
    if (e < NE) atomicAdd(&g_cnt[rows[e]], 1);
}

__global__ __launch_bounds__(1024) void scanA_kernel() {
    __shared__ int sm[1024];
    const int t = threadIdx.x;
    const int i = blockIdx.x * 1024 + t;
    const int v = (i < MN) ? g_cnt[i] : 0;
    sm[t] = v;
    __syncthreads();
    #pragma unroll
    for (int off = 1; off < 1024; off <<= 1) {
        int u = (t >= off) ? sm[t - off] : 0;
        __syncthreads();
        sm[t] += u;
        __syncthreads();
    }
    if (i < MN) g_incl[i] = sm[t];
    if (t == 1023) g_bsum[blockIdx.x] = sm[1023];
}

__global__ __launch_bounds__(64) void scanB_kernel() {
    __shared__ int sm[64];
    const int t = threadIdx.x;
    const int v = (t < NB_SCAN) ? g_bsum[t] : 0;
    sm[t] = v;
    __syncthreads();
    #pragma unroll
    for (int off = 1; off < 64; off <<= 1) {
        int u = (t >= off) ? sm[t - off] : 0;
        __syncthreads();
        sm[t] += u;
        __syncthreads();
    }
    g_bpre[t] = sm[t] - v;
}

__global__ __launch_bounds__(1024) void scanC_kernel() {
    const int i = blockIdx.x * 1024 + threadIdx.x;
    if (i < MN) {
        const int off = g_incl[i] - g_cnt[i] + g_bpre[blockIdx.x];
        g_off[i] = off;
        g_cur[i] = off;
    }
    if (i == 0) g_off[MN] = NE;
}

__global__ __launch_bounds__(256) void fill_kernel(const int* __restrict__ rows) {
    int e = blockIdx.x * 256 + threadIdx.x;
    if (e < NE) {
        int pos = atomicAdd(&g_cur[rows[e]], 1);
        g_eid[pos] = e;
    }
}

// ---------------------------------------------------------------------------
// Accumulate: one warp per output row. Lane handles 4 cols as half4 (8B gather),
// fp32 register accumulation, fused ReLU, fp32 store.
// ---------------------------------------------------------------------------
__global__ __launch_bounds__(256) void acc_kernel(const float* __restrict__ vals,
                                                  const int* __restrict__ cols,
                                                  float* __restrict__ out) {
    const int r = blockIdx.x * 8 + (threadIdx.x >> 5);
    if (r >= MN) return;
    const int lane = threadIdx.x & 31;

    const int beg = g_off[r];
    const int end = g_off[r + 1];

    float4 acc = make_float4(0.f, 0.f, 0.f, 0.f);

    int i = beg;
    for (; i + 1 < end; i += 2) {
        const int e0 = __ldg(&g_eid[i]);
        const int e1 = __ldg(&g_eid[i + 1]);
        const float v0 = __ldg(&vals[e0]);
        const float v1 = __ldg(&vals[e1]);
        const int c0 = __ldg(&cols[e0]);
        const int c1 = __ldg(&cols[e1]);
        const uint2 r0 = __ldg(reinterpret_cast<const uint2*>(g_support_h + (size_t)c0 * NF) + lane);
        const uint2 r1 = __ldg(reinterpret_cast<const uint2*>(g_support_h + (size_t)c1 * NF) + lane);
        const float2 a0 = __half22float2(*reinterpret_cast<const __half2*>(&r0.x));
        const float2 b0 = __half22float2(*reinterpret_cast<const __half2*>(&r0.y));
        const float2 a1 = __half22float2(*reinterpret_cast<const __half2*>(&r1.x));
        const float2 b1 = __half22float2(*reinterpret_cast<const __half2*>(&r1.y));
        acc.x = fmaf(v0, a0.x, acc.x);
        acc.y = fmaf(v0, a0.y, acc.y);
        acc.z = fmaf(v0, b0.x, acc.z);
        acc.w = fmaf(v0, b0.y, acc.w);
        acc.x = fmaf(v1, a1.x, acc.x);
        acc.y = fmaf(v1, a1.y, acc.y);
        acc.z = fmaf(v1, b1.x, acc.z);
        acc.w = fmaf(v1, b1.y, acc.w);
    }
    if (i < end) {
        const int e0 = __ldg(&g_eid[i]);
        const float v0 = __ldg(&vals[e0]);
        const int c0 = __ldg(&cols[e0]);
        const uint2 r0 = __ldg(reinterpret_cast<const uint2*>(g_support_h + (size_t)c0 * NF) + lane);
        const float2 a0 = __half22float2(*reinterpret_cast<const __half2*>(&r0.x));
        const float2 b0 = __half22float2(*reinterpret_cast<const __half2*>(&r0.y));
        acc.x = fmaf(v0, a0.x, acc.x);
        acc.y = fmaf(v0, a0.y, acc.y);
        acc.z = fmaf(v0, b0.x, acc.z);
        acc.w = fmaf(v0, b0.y, acc.w);
    }

    float4 o;
    o.x = fmaxf(acc.x, 0.f);
    o.y = fmaxf(acc.y, 0.f);
    o.z = fmaxf(acc.z, 0.f);
    o.w = fmaxf(acc.w, 0.f);
    *(reinterpret_cast<float4*>(out + (size_t)r * NF) + lane) = o;
}

// ---------------------------------------------------------------------------
// Launch: CSR build forked onto a side stream, overlapped with the GEMM.
// ---------------------------------------------------------------------------
static cudaStream_t s_side = nullptr;
static cudaEvent_t  s_evFork = nullptr;
static cudaEvent_t  s_evJoin = nullptr;

extern "C" void kernel_launch(void* const* d_in, const int* in_sizes, int n_in,
                              void* d_out, int out_size) {
    const float* x    = (const float*)d_in[0];
    const float* w    = (const float*)d_in[1];
    const float* vals = (const float*)d_in[2];
    const int*   rows = (const int*)d_in[3];
    const int*   cols = (const int*)d_in[4];
    float* out = (float*)d_out;

    if (!s_side) {
        cudaStreamCreateWithFlags(&s_side, cudaStreamNonBlocking);
        cudaEventCreateWithFlags(&s_evFork, cudaEventDisableTiming);
        cudaEventCreateWithFlags(&s_evJoin, cudaEventDisableTiming);
    }

    // fork: CSR build on side stream
    cudaEventRecord(s_evFork, 0);
    cudaStreamWaitEvent(s_side, s_evFork, 0);

    zero_cnt_kernel<<<(MN + 255) / 256, 256, 0, s_side>>>();
    hist_kernel<<<(NE + 255) / 256, 256, 0, s_side>>>(rows);
    scanA_kernel<<<NB_SCAN, 1024, 0, s_side>>>();
    scanB_kernel<<<1, 64, 0, s_side>>>();
    scanC_kernel<<<NB_SCAN, 1024, 0, s_side>>>();
    fill_kernel<<<(NE + 255) / 256, 256, 0, s_side>>>(rows);
    cudaEventRecord(s_evJoin, s_side);

    // main stream: GEMM (independent of CSR build)
    gemm_kernel<<<(MN + 127) / 128, 256>>>(x, w);

    // join, then accumulate
    cudaStreamWaitEvent(0, s_evJoin, 0);
    acc_kernel<<<(MN + 7) / 8, 256>>>(vals, cols, out);
}

// round 11
// speedup vs baseline: 1.5060x; 1.0681x over previous
#include <cuda_runtime.h>
#include <cuda_bf16.h>
#include <cuda_fp16.h>

#define MN 50000      // nodes
#define KF 256        // in features
#define NF 128        // out features
#define NE 800000     // edges

#define NB_SCAN ((MN + 1023) / 1024)   // 49 scan blocks

// scratch
__device__ __half g_support_h[(size_t)MN * NF];   // x @ W in fp16 (12.8 MB)
__device__ int2  g_vc[NE];                        // row-sorted (val_bits, col)
__device__ int   g_cnt[MN];
__device__ int   g_incl[MN];
__device__ int   g_bsum[64];
__device__ int   g_bpre[64];
__device__ int   g_cur[MN];
__device__ int   g_off[MN + 1];

// ---------------------------------------------------------------------------
// bf16 split helpers: f = hi + lo (each bf16), pack two k-adjacent elements
// into one 32-bit word (low half = even k, high half = odd k).
// ---------------------------------------------------------------------------
__device__ __forceinline__ void split2(float f0, float f1, unsigned& hi, unsigned& lo) {
    __nv_bfloat16 h0 = __float2bfloat16(f0);
    __nv_bfloat16 h1 = __float2bfloat16(f1);
    __nv_bfloat16 l0 = __float2bfloat16(f0 - __bfloat162float(h0));
    __nv_bfloat16 l1 = __float2bfloat16(f1 - __bfloat162float(h1));
    hi = (unsigned)__bfloat16_as_ushort(h0) | ((unsigned)__bfloat16_as_ushort(h1) << 16);
    lo = (unsigned)__bfloat16_as_ushort(l0) | ((unsigned)__bfloat16_as_ushort(l1) << 16);
}

__device__ __forceinline__ void mma_bf16(float d[4], const unsigned a[4],
                                         unsigned b0, unsigned b1) {
    asm volatile(
        "mma.sync.aligned.m16n8k16.row.col.f32.bf16.bf16.f32 "
        "{%0,%1,%2,%3}, {%4,%5,%6,%7}, {%8,%9}, {%0,%1,%2,%3};"
        : "+f"(d[0]), "+f"(d[1]), "+f"(d[2]), "+f"(d[3])
        : "r"(a[0]), "r"(a[1]), "r"(a[2]), "r"(a[3]), "r"(b0), "r"(b1));
}

// ---------------------------------------------------------------------------
// GEMM: support[MN,NF] = x[MN,KF] @ w[KF,NF]  via split-bf16 m16n8k16 MMA.
// 128x128 CTA tile, BK=16, 8 warps (4Mx2N), warp tile 32x64.
// D += Ahi*Bhi + Ahi*Blo + Alo*Bhi   (rel err ~1e-5); output stored fp16.
// ---------------------------------------------------------------------------
__global__ __launch_bounds__(256, 2) void gemm_kernel(const float* __restrict__ x,
                                                      const float* __restrict__ w) {
    __shared__ unsigned As_hi[128][12], As_lo[128][12];   // [m][k/2], 8 words + pad 4
    __shared__ unsigned Bs_hi[8][136], Bs_lo[8][136];     // [k/2][n], 128 + pad 8

    const int tid = threadIdx.x;
    const int wid = tid >> 5;
    const int lane = tid & 31;
    const int grp = lane >> 2;     // 0..7
    const int tig = lane & 3;      // 0..3
    const int warpM = wid >> 1;    // 0..3
    const int warpN = wid & 1;     // 0..1
    const int blockRow = blockIdx.x * 128;

    const int xr0 = tid >> 2;
    const int xr1 = xr0 + 64;
    const int xc  = (tid & 3) * 4;
    const int xw  = (tid & 3) * 2;
    const int xg0 = min(blockRow + xr0, MN - 1);
    const int xg1 = min(blockRow + xr1, MN - 1);
    const int wr0 = (tid >> 5) * 2;
    const int wc  = (tid & 31) * 4;

    float d[2][8][4];
    #pragma unroll
    for (int mt = 0; mt < 2; mt++)
        #pragma unroll
        for (int nt = 0; nt < 8; nt++)
            #pragma unroll
            for (int i = 0; i < 4; i++) d[mt][nt][i] = 0.0f;

    float4 xa = *reinterpret_cast<const float4*>(&x[(size_t)xg0 * KF + xc]);
    float4 xb = *reinterpret_cast<const float4*>(&x[(size_t)xg1 * KF + xc]);
    float4 wa = *reinterpret_cast<const float4*>(&w[(size_t)wr0 * NF + wc]);
    float4 wb = *reinterpret_cast<const float4*>(&w[(size_t)(wr0 + 1) * NF + wc]);

    #pragma unroll 1
    for (int kt = 0; kt < KF; kt += 16) {
        {
            unsigned h, l;
            split2(xa.x, xa.y, h, l); As_hi[xr0][xw + 0] = h; As_lo[xr0][xw + 0] = l;
            split2(xa.z, xa.w, h, l); As_hi[xr0][xw + 1] = h; As_lo[xr0][xw + 1] = l;
            split2(xb.x, xb.y, h, l); As_hi[xr1][xw + 0] = h; As_lo[xr1][xw + 0] = l;
            split2(xb.z, xb.w, h, l); As_hi[xr1][xw + 1] = h; As_lo[xr1][xw + 1] = l;
            const int bw = tid >> 5;
            split2(wa.x, wb.x, h, l); Bs_hi[bw][wc + 0] = h; Bs_lo[bw][wc + 0] = l;
            split2(wa.y, wb.y, h, l); Bs_hi[bw][wc + 1] = h; Bs_lo[bw][wc + 1] = l;
            split2(wa.z, wb.z, h, l); Bs_hi[bw][wc + 2] = h; Bs_lo[bw][wc + 2] = l;
            split2(wa.w, wb.w, h, l); Bs_hi[bw][wc + 3] = h; Bs_lo[bw][wc + 3] = l;
        }
        __syncthreads();

        const bool has_next = (kt + 16) < KF;
        if (has_next) {
            xa = *reinterpret_cast<const float4*>(&x[(size_t)xg0 * KF + kt + 16 + xc]);
            xb = *reinterpret_cast<const float4*>(&x[(size_t)xg1 * KF + kt + 16 + xc]);
            wa = *reinterpret_cast<const float4*>(&w[(size_t)(kt + 16 + wr0) * NF + wc]);
            wb = *reinterpret_cast<const float4*>(&w[(size_t)(kt + 16 + wr0 + 1) * NF + wc]);
        }

        unsigned ah[2][4], al[2][4];
        #pragma unroll
        for (int mt = 0; mt < 2; mt++) {
            const int rb = warpM * 32 + mt * 16;
            ah[mt][0] = As_hi[rb + grp][tig];
            ah[mt][1] = As_hi[rb + grp + 8][tig];
            ah[mt][2] = As_hi[rb + grp][tig + 4];
            ah[mt][3] = As_hi[rb + grp + 8][tig + 4];
            al[mt][0] = As_lo[rb + grp][tig];
            al[mt][1] = As_lo[rb + grp + 8][tig];
            al[mt][2] = As_lo[rb + grp][tig + 4];
            al[mt][3] = As_lo[rb + grp + 8][tig + 4];
        }

        #pragma unroll
        for (int nt = 0; nt < 8; nt++) {
            const int cb = warpN * 64 + nt * 8 + grp;
            const unsigned bh0 = Bs_hi[tig][cb];
            const unsigned bh1 = Bs_hi[tig + 4][cb];
            const unsigned bl0 = Bs_lo[tig][cb];
            const unsigned bl1 = Bs_lo[tig + 4][cb];
            #pragma unroll
            for (int mt = 0; mt < 2; mt++) {
                mma_bf16(d[mt][nt], ah[mt], bl0, bl1);   // hi*lo
                mma_bf16(d[mt][nt], al[mt], bh0, bh1);   // lo*hi
                mma_bf16(d[mt][nt], ah[mt], bh0, bh1);   // hi*hi
            }
        }
        __syncthreads();
    }

    #pragma unroll
    for (int mt = 0; mt < 2; mt++) {
        const int r0 = blockRow + warpM * 32 + mt * 16 + grp;
        const int r1 = r0 + 8;
        #pragma unroll
        for (int nt = 0; nt < 8; nt++) {
            const int col = warpN * 64 + nt * 8 + 2 * tig;
            if (r0 < MN)
                *reinterpret_cast<__half2*>(&g_support_h[(size_t)r0 * NF + col]) =
                    __floats2half2_rn(d[mt][nt][0], d[mt][nt][1]);
            if (r1 < MN)
                *reinterpret_cast<__half2*>(&g_support_h[(size_t)r1 * NF + col]) =
                    __floats2half2_rn(d[mt][nt][2], d[mt][nt][3]);
        }
    }
}

// ---------------------------------------------------------------------------
// CSR build
// ---------------------------------------------------------------------------
__global__ __launch_bounds__(256) void zero_cnt_kernel() {
    int i = blockIdx.x * 256 + threadIdx.x;
    if (i < MN) g_cnt[i] = 0;
}

__global__ __launch_bounds__(256) void hist_kernel(const int* __restrict__ rows) {
    int e = blockIdx.x * 256 + threadIdx.x;
    if (e < NE) atomicAdd(&g_cnt[rows[e]], 1);
}

__global__ __launch_bounds__(1024) void scanA_kernel() {
    __shared__ int sm[1024];
    const int t = threadIdx.x;
    const int i = blockIdx.x * 1024 + t;
    const int v = (i < MN) ? g_cnt[i] : 0;
    sm[t] = v;
    __syncthreads();
    #pragma unroll
    for (int off = 1; off < 1024; off <<= 1) {
        int u = (t >= off) ? sm[t - off] : 0;
        __syncthreads();
        sm[t] += u;
        __syncthreads();
    }
    if (i < MN) g_incl[i] = sm[t];
    if (t == 1023) g_bsum[blockIdx.x] = sm[1023];
}

__global__ __launch_bounds__(64) void scanB_kernel() {
    __shared__ int sm[64];
    const int t = threadIdx.x;
    const int v = (t < NB_SCAN) ? g_bsum[t] : 0;
    sm[t] = v;
    __syncthreads();
    #pragma unroll
    for (int off = 1; off < 64; off <<= 1) {
        int u = (t >= off) ? sm[t - off] : 0;
        __syncthreads();
        sm[t] += u;
        __syncthreads();
    }
    g_bpre[t] = sm[t] - v;
}

__global__ __launch_bounds__(1024) void scanC_kernel() {
    const int i = blockIdx.x * 1024 + threadIdx.x;
    if (i < MN) {
        const int off = g_incl[i] - g_cnt[i] + g_bpre[blockIdx.x];
        g_off[i] = off;
        g_cur[i] = off;
    }
    if (i == 0) g_off[MN] = NE;
}

// fill: write sorted (val, col) payload directly -- no eid indirection later
__global__ __launch_bounds__(256) void fill_kernel(const int* __restrict__ rows,
                                                   const float* __restrict__ vals,
                                                   const int* __restrict__ cols) {
    int e = blockIdx.x * 256 + threadIdx.x;
    if (e < NE) {
        const int r = rows[e];
        const float v = vals[e];
        const int c = cols[e];
        int pos = atomicAdd(&g_cur[r], 1);
        g_vc[pos] = make_int2(__float_as_int(v), c);
    }
}

// ---------------------------------------------------------------------------
// Accumulate: one warp per output row. Metadata for up to 32 edges is loaded
// with ONE coalesced 8B/lane load, then broadcast via shfl; each lane gathers
// 4 cols (fp16) per edge. fp32 accum, fused ReLU, fp32 store.
// ---------------------------------------------------------------------------
__global__ __launch_bounds__(256) void acc_kernel(float* __restrict__ out) {
    const int r = blockIdx.x * 8 + (threadIdx.x >> 5);
    if (r >= MN) return;
    const int lane = threadIdx.x & 31;

    const int beg = g_off[r];
    const int end = g_off[r + 1];

    float4 acc = make_float4(0.f, 0.f, 0.f, 0.f);

    for (int base = beg; base < end; base += 32) {
        const int m = min(32, end - base);
        int2 vc = make_int2(0, 0);
        if (base + lane < end) vc = __ldg(&g_vc[base + lane]);
        const float vv = __int_as_float(vc.x);

        int j = 0;
        for (; j + 2 <= m; j += 2) {
            const float v0 = __shfl_sync(0xFFFFFFFFu, vv, j);
            const int   c0 = __shfl_sync(0xFFFFFFFFu, vc.y, j);
            const float v1 = __shfl_sync(0xFFFFFFFFu, vv, j + 1);
            const int   c1 = __shfl_sync(0xFFFFFFFFu, vc.y, j + 1);
            const uint2 q0 = __ldg(reinterpret_cast<const uint2*>(g_support_h + (size_t)c0 * NF) + lane);
            const uint2 q1 = __ldg(reinterpret_cast<const uint2*>(g_support_h + (size_t)c1 * NF) + lane);
            const float2 a0 = __half22float2(*reinterpret_cast<const __half2*>(&q0.x));
            const float2 b0 = __half22float2(*reinterpret_cast<const __half2*>(&q0.y));
            const float2 a1 = __half22float2(*reinterpret_cast<const __half2*>(&q1.x));
            const float2 b1 = __half22float2(*reinterpret_cast<const __half2*>(&q1.y));
            acc.x = fmaf(v0, a0.x, acc.x);
            acc.y = fmaf(v0, a0.y, acc.y);
            acc.z = fmaf(v0, b0.x, acc.z);
            acc.w = fmaf(v0, b0.y, acc.w);
            acc.x = fmaf(v1, a1.x, acc.x);
            acc.y = fmaf(v1, a1.y, acc.y);
            acc.z = fmaf(v1, b1.x, acc.z);
            acc.w = fmaf(v1, b1.y, acc.w);
        }
        if (j < m) {
            const float v0 = __shfl_sync(0xFFFFFFFFu, vv, j);
            const int   c0 = __shfl_sync(0xFFFFFFFFu, vc.y, j);
            const uint2 q0 = __ldg(reinterpret_cast<const uint2*>(g_support_h + (size_t)c0 * NF) + lane);
            const float2 a0 = __half22float2(*reinterpret_cast<const __half2*>(&q0.x));
            const float2 b0 = __half22float2(*reinterpret_cast<const __half2*>(&q0.y));
            acc.x = fmaf(v0, a0.x, acc.x);
            acc.y = fmaf(v0, a0.y, acc.y);
            acc.z = fmaf(v0, b0.x, acc.z);
            acc.w = fmaf(v0, b0.y, acc.w);
        }
    }

    float4 o;
    o.x = fmaxf(acc.x, 0.f);
    o.y = fmaxf(acc.y, 0.f);
    o.z = fmaxf(acc.z, 0.f);
    o.w = fmaxf(acc.w, 0.f);
    *(reinterpret_cast<float4*>(out + (size_t)r * NF) + lane) = o;
}

// ---------------------------------------------------------------------------
// Launch: CSR build forked onto a side stream, overlapped with the GEMM.
// ---------------------------------------------------------------------------
static cudaStream_t s_side = nullptr;
static cudaEvent_t  s_evFork = nullptr;
static cudaEvent_t  s_evJoin = nullptr;

extern "C" void kernel_launch(void* const* d_in, const int* in_sizes, int n_in,
                              void* d_out, int out_size) {
    const float* x    = (const float*)d_in[0];
    const float* w    = (const float*)d_in[1];
    const float* vals = (const float*)d_in[2];
    const int*   rows = (const int*)d_in[3];
    const int*   cols = (const int*)d_in[4];
    float* out = (float*)d_out;

    if (!s_side) {
        cudaStreamCreateWithFlags(&s_side, cudaStreamNonBlocking);
        cudaEventCreateWithFlags(&s_evFork, cudaEventDisableTiming);
        cudaEventCreateWithFlags(&s_evJoin, cudaEventDisableTiming);
    }

    // fork: CSR build on side stream
    cudaEventRecord(s_evFork, 0);
    cudaStreamWaitEvent(s_side, s_evFork, 0);

    zero_cnt_kernel<<<(MN + 255) / 256, 256, 0, s_side>>>();
    hist_kernel<<<(NE + 255) / 256, 256, 0, s_side>>>(rows);
    scanA_kernel<<<NB_SCAN, 1024, 0, s_side>>>();
    scanB_kernel<<<1, 64, 0, s_side>>>();
    scanC_kernel<<<NB_SCAN, 1024, 0, s_side>>>();
    fill_kernel<<<(NE + 255) / 256, 256, 0, s_side>>>(rows, vals, cols);
    cudaEventRecord(s_evJoin, s_side);

    // main stream: GEMM (independent of CSR build)
    gemm_kernel<<<(MN + 127) / 128, 256>>>(x, w);

    // join, then accumulate
    cudaStreamWaitEvent(0, s_evJoin, 0);
    acc_kernel<<<(MN + 7) / 8, 256>>>(out);
}

// round 12
// speedup vs baseline: 1.6021x; 1.0638x over previous
#include <cuda_runtime.h>
#include <cuda_fp16.h>

#define MN 50000      // nodes
#define KF 256        // in features
#define NF 128        // out features
#define NE 800000     // edges

#define NB_SCAN ((MN + 1023) / 1024)   // 49 scan blocks

// scratch
__device__ __half g_support_h[(size_t)MN * NF];   // x @ W in fp16 (12.8 MB)
__device__ int2  g_vc[NE];                        // row-sorted (val_bits, col)
__device__ int   g_cnt[MN];
__device__ int   g_incl[MN];
__device__ int   g_bsum[64];
__device__ int   g_bpre[64];
__device__ int   g_cur[MN];
__device__ int   g_off[MN + 1];

// ---------------------------------------------------------------------------
// fp16 helpers: pack two k-adjacent fp32 into one half2 word
// ---------------------------------------------------------------------------
__device__ __forceinline__ unsigned pack2(float f0, float f1) {
    __half2 h = __floats2half2_rn(f0, f1);
    return *reinterpret_cast<unsigned*>(&h);
}

__device__ __forceinline__ void mma_fp16(float d[4], const unsigned a[4],
                                         unsigned b0, unsigned b1) {
    asm volatile(
        "mma.sync.aligned.m16n8k16.row.col.f32.f16.f16.f32 "
        "{%0,%1,%2,%3}, {%4,%5,%6,%7}, {%8,%9}, {%0,%1,%2,%3};"
        : "+f"(d[0]), "+f"(d[1]), "+f"(d[2]), "+f"(d[3])
        : "r"(a[0]), "r"(a[1]), "r"(a[2]), "r"(a[3]), "r"(b0), "r"(b1));
}

// ---------------------------------------------------------------------------
// GEMM: support[MN,NF] = x[MN,KF] @ w[KF,NF]  via fp16 m16n8k16 MMA.
// 128x128 CTA tile, BK=16, 8 warps (4Mx2N), warp tile 32x64.
// Single-term fp16 (rel err ~2e-4); output stored fp16.
// SMEM words (k-packed pairs): A[m][k/2] stride 12, B[k/2][n] stride 136
// (both verified conflict-free for the fragment-load patterns).
// ---------------------------------------------------------------------------
__global__ __launch_bounds__(256, 3) void gemm_kernel(const float* __restrict__ x,
                                                      const float* __restrict__ w) {
    __shared__ unsigned As[128][12];   // [m][k/2], 8 words + pad 4
    __shared__ unsigned Bs[8][136];    // [k/2][n], 128 + pad 8

    const int tid = threadIdx.x;
    const int wid = tid >> 5;
    const int lane = tid & 31;
    const int grp = lane >> 2;     // 0..7
    const int tig = lane & 3;      // 0..3
    const int warpM = wid >> 1;    // 0..3
    const int warpN = wid & 1;     // 0..1
    const int blockRow = blockIdx.x * 128;

    const int xr0 = tid >> 2;                 // 0..63
    const int xr1 = xr0 + 64;                 // 64..127
    const int xc  = (tid & 3) * 4;            // k offset: 0,4,8,12
    const int xw  = (tid & 3) * 2;            // word col: 0,2,4,6
    const int xg0 = min(blockRow + xr0, MN - 1);
    const int xg1 = min(blockRow + xr1, MN - 1);
    const int wr0 = (tid >> 5) * 2;           // even k row
    const int wc  = (tid & 31) * 4;           // 0..124

    float d[2][8][4];
    #pragma unroll
    for (int mt = 0; mt < 2; mt++)
        #pragma unroll
        for (int nt = 0; nt < 8; nt++)
            #pragma unroll
            for (int i = 0; i < 4; i++) d[mt][nt][i] = 0.0f;

    // prologue: load tile 0
    float4 xa = *reinterpret_cast<const float4*>(&x[(size_t)xg0 * KF + xc]);
    float4 xb = *reinterpret_cast<const float4*>(&x[(size_t)xg1 * KF + xc]);
    float4 wa = *reinterpret_cast<const float4*>(&w[(size_t)wr0 * NF + wc]);
    float4 wb = *reinterpret_cast<const float4*>(&w[(size_t)(wr0 + 1) * NF + wc]);

    #pragma unroll 1
    for (int kt = 0; kt < KF; kt += 16) {
        // stage current tile (fp16 pack, k-pairs)
        As[xr0][xw + 0] = pack2(xa.x, xa.y);
        As[xr0][xw + 1] = pack2(xa.z, xa.w);
        As[xr1][xw + 0] = pack2(xb.x, xb.y);
        As[xr1][xw + 1] = pack2(xb.z, xb.w);
        {
            const int bw = tid >> 5;   // word row = k/2
            Bs[bw][wc + 0] = pack2(wa.x, wb.x);
            Bs[bw][wc + 1] = pack2(wa.y, wb.y);
            Bs[bw][wc + 2] = pack2(wa.z, wb.z);
            Bs[bw][wc + 3] = pack2(wa.w, wb.w);
        }
        __syncthreads();

        // prefetch next tile into registers
        const bool has_next = (kt + 16) < KF;
        if (has_next) {
            xa = *reinterpret_cast<const float4*>(&x[(size_t)xg0 * KF + kt + 16 + xc]);
            xb = *reinterpret_cast<const float4*>(&x[(size_t)xg1 * KF + kt + 16 + xc]);
            wa = *reinterpret_cast<const float4*>(&w[(size_t)(kt + 16 + wr0) * NF + wc]);
            wb = *reinterpret_cast<const float4*>(&w[(size_t)(kt + 16 + wr0 + 1) * NF + wc]);
        }

        // A fragments for both m-tiles
        unsigned a[2][4];
        #pragma unroll
        for (int mt = 0; mt < 2; mt++) {
            const int rb = warpM * 32 + mt * 16;
            a[mt][0] = As[rb + grp][tig];
            a[mt][1] = As[rb + grp + 8][tig];
            a[mt][2] = As[rb + grp][tig + 4];
            a[mt][3] = As[rb + grp + 8][tig + 4];
        }

        #pragma unroll
        for (int nt = 0; nt < 8; nt++) {
            const int cb = warpN * 64 + nt * 8 + grp;
            const unsigned b0 = Bs[tig][cb];
            const unsigned b1 = Bs[tig + 4][cb];
            #pragma unroll
            for (int mt = 0; mt < 2; mt++)
                mma_fp16(d[mt][nt], a[mt], b0, b1);
        }
        __syncthreads();
    }

    // epilogue: write support as fp16 (half2 stores)
    #pragma unroll
    for (int mt = 0; mt < 2; mt++) {
        const int r0 = blockRow + warpM * 32 + mt * 16 + grp;
        const int r1 = r0 + 8;
        #pragma unroll
        for (int nt = 0; nt < 8; nt++) {
            const int col = warpN * 64 + nt * 8 + 2 * tig;
            if (r0 < MN)
                *reinterpret_cast<__half2*>(&g_support_h[(size_t)r0 * NF + col]) =
                    __floats2half2_rn(d[mt][nt][0], d[mt][nt][1]);
            if (r1 < MN)
                *reinterpret_cast<__half2*>(&g_support_h[(size_t)r1 * NF + col]) =
                    __floats2half2_rn(d[mt][nt][2], d[mt][nt][3]);
        }
    }
}

// ---------------------------------------------------------------------------
// CSR build
// ---------------------------------------------------------------------------
__global__ __launch_bounds__(256) void zero_cnt_kernel() {
    int i = blockIdx.x * 256 + threadIdx.x;
    if (i < MN) g_cnt[i] = 0;
}

__global__ __launch_bounds__(256) void hist_kernel(const int* __restrict__ rows) {
    int e = blockIdx.x * 256 + threadIdx.x;
    if (e < NE) atomicAdd(&g_cnt[rows[e]], 1);
}

__global__ __launch_bounds__(1024) void scanA_kernel() {
    __shared__ int sm[1024];
    const int t = threadIdx.x;
    const int i = blockIdx.x * 1024 + t;
    const int v = (i < MN) ? g_cnt[i] : 0;
    sm[t] = v;
    __syncthreads();
    #pragma unroll
    for (int off = 1; off < 1024; off <<= 1) {
        int u = (t >= off) ? sm[t - off] : 0;
        __syncthreads();
        sm[t] += u;
        __syncthreads();
    }
    if (i < MN) g_incl[i] = sm[t];
    if (t == 1023) g_bsum[blockIdx.x] = sm[1023];
}

__global__ __launch_bounds__(64) void scanB_kernel() {
    __shared__ int sm[64];
    const int t = threadIdx.x;
    const int v = (t < NB_SCAN) ? g_bsum[t] : 0;
    sm[t] = v;
    __syncthreads();
    #pragma unroll
    for (int off = 1; off < 64; off <<= 1) {
        int u = (t >= off) ? sm[t - off] : 0;
        __syncthreads();
        sm[t] += u;
        __syncthreads();
    }
    g_bpre[t] = sm[t] - v;
}

__global__ __launch_bounds__(1024) void scanC_kernel() {
    const int i = blockIdx.x * 1024 + threadIdx.x;
    if (i < MN) {
        const int off = g_incl[i] - g_cnt[i] + g_bpre[blockIdx.x];
        g_off[i] = off;
        g_cur[i] = off;
    }
    if (i == 0) g_off[MN] = NE;
}

// fill: write sorted (val, col) payload directly -- no eid indirection later
__global__ __launch_bounds__(256) void fill_kernel(const int* __restrict__ rows,
                                                   const float* __restrict__ vals,
                                                   const int* __restrict__ cols) {
    int e = blockIdx.x * 256 + threadIdx.x;
    if (e < NE) {
        const int r = rows[e];
        const float v = vals[e];
        const int c = cols[e];
        int pos = atomicAdd(&g_cur[r], 1);
        g_vc[pos] = make_int2(__float_as_int(v), c);
    }
}

// ---------------------------------------------------------------------------
// Accumulate: one warp per output row. Metadata for up to 32 edges loaded
// with ONE coalesced 8B/lane load, broadcast via shfl; each lane gathers
// 4 cols (fp16) per edge. fp32 accum, fused ReLU, fp32 store.
// ---------------------------------------------------------------------------
__global__ __launch_bounds__(256) void acc_kernel(float* __restrict__ out) {
    const int r = blockIdx.x * 8 + (threadIdx.x >> 5);
    if (r >= MN) return;
    const int lane = threadIdx.x & 31;

    const int beg = g_off[r];
    const int end = g_off[r + 1];

    float4 acc = make_float4(0.f, 0.f, 0.f, 0.f);

    for (int base = beg; base < end; base += 32) {
        const int m = min(32, end - base);
        int2 vc = make_int2(0, 0);
        if (base + lane < end) vc = __ldg(&g_vc[base + lane]);
        const float vv = __int_as_float(vc.x);

        int j = 0;
        for (; j + 2 <= m; j += 2) {
            const float v0 = __shfl_sync(0xFFFFFFFFu, vv, j);
            const int   c0 = __shfl_sync(0xFFFFFFFFu, vc.y, j);
            const float v1 = __shfl_sync(0xFFFFFFFFu, vv, j + 1);
            const int   c1 = __shfl_sync(0xFFFFFFFFu, vc.y, j + 1);
            const uint2 q0 = __ldg(reinterpret_cast<const uint2*>(g_support_h + (size_t)c0 * NF) + lane);
            const uint2 q1 = __ldg(reinterpret_cast<const uint2*>(g_support_h + (size_t)c1 * NF) + lane);
            const float2 a0 = __half22float2(*reinterpret_cast<const __half2*>(&q0.x));
            const float2 b0 = __half22float2(*reinterpret_cast<const __half2*>(&q0.y));
            const float2 a1 = __half22float2(*reinterpret_cast<const __half2*>(&q1.x));
            const float2 b1 = __half22float2(*reinterpret_cast<const __half2*>(&q1.y));
            acc.x = fmaf(v0, a0.x, acc.x);
            acc.y = fmaf(v0, a0.y, acc.y);
            acc.z = fmaf(v0, b0.x, acc.z);
            acc.w = fmaf(v0, b0.y, acc.w);
            acc.x = fmaf(v1, a1.x, acc.x);
            acc.y = fmaf(v1, a1.y, acc.y);
            acc.z = fmaf(v1, b1.x, acc.z);
            acc.w = fmaf(v1, b1.y, acc.w);
        }
        if (j < m) {
            const float v0 = __shfl_sync(0xFFFFFFFFu, vv, j);
            const int   c0 = __shfl_sync(0xFFFFFFFFu, vc.y, j);
            const uint2 q0 = __ldg(reinterpret_cast<const uint2*>(g_support_h + (size_t)c0 * NF) + lane);
            const float2 a0 = __half22float2(*reinterpret_cast<const __half2*>(&q0.x));
            const float2 b0 = __half22float2(*reinterpret_cast<const __half2*>(&q0.y));
            acc.x = fmaf(v0, a0.x, acc.x);
            acc.y = fmaf(v0, a0.y, acc.y);
            acc.z = fmaf(v0, b0.x, acc.z);
            acc.w = fmaf(v0, b0.y, acc.w);
        }
    }

    float4 o;
    o.x = fmaxf(acc.x, 0.f);
    o.y = fmaxf(acc.y, 0.f);
    o.z = fmaxf(acc.z, 0.f);
    o.w = fmaxf(acc.w, 0.f);
    *(reinterpret_cast<float4*>(out + (size_t)r * NF) + lane) = o;
}

// ---------------------------------------------------------------------------
// Launch: CSR build forked onto a side stream, overlapped with the GEMM.
// ---------------------------------------------------------------------------
static cudaStream_t s_side = nullptr;
static cudaEvent_t  s_evFork = nullptr;
static cudaEvent_t  s_evJoin = nullptr;

extern "C" void kernel_launch(void* const* d_in, const int* in_sizes, int n_in,
                              void* d_out, int out_size) {
    const float* x    = (const float*)d_in[0];
    const float* w    = (const float*)d_in[1];
    const float* vals = (const float*)d_in[2];
    const int*   rows = (const int*)d_in[3];
    const int*   cols = (const int*)d_in[4];
    float* out = (float*)d_out;

    if (!s_side) {
        cudaStreamCreateWithFlags(&s_side, cudaStreamNonBlocking);
        cudaEventCreateWithFlags(&s_evFork, cudaEventDisableTiming);
        cudaEventCreateWithFlags(&s_evJoin, cudaEventDisableTiming);
    }

    // fork: CSR build on side stream
    cudaEventRecord(s_evFork, 0);
    cudaStreamWaitEvent(s_side, s_evFork, 0);

    zero_cnt_kernel<<<(MN + 255) / 256, 256, 0, s_side>>>();
    hist_kernel<<<(NE + 255) / 256, 256, 0, s_side>>>(rows);
    scanA_kernel<<<NB_SCAN, 1024, 0, s_side>>>();
    scanB_kernel<<<1, 64, 0, s_side>>>();
    scanC_kernel<<<NB_SCAN, 1024, 0, s_side>>>();
    fill_kernel<<<(NE + 255) / 256, 256, 0, s_side>>>(rows, vals, cols);
    cudaEventRecord(s_evJoin, s_side);

    // main stream: GEMM (independent of CSR build)
    gemm_kernel<<<(MN + 127) / 128, 256>>>(x, w);

    // join, then accumulate
    cudaStreamWaitEvent(0, s_evJoin, 0);
    acc_kernel<<<(MN + 7) / 8, 256>>>(out);
}